// round 1
// baseline (speedup 1.0000x reference)
#include <cuda_runtime.h>
#include <cuda_bf16.h>
#include <math_constants.h>

// Problem constants
#define NN      50000
#define EE      800000
#define IN_DIM  256
#define HD      256      // NHEAD * OUT_DIM
#define OUT_DIM 64
#define NHEAD   4
#define SLOPE   0.2f
#define BN_EPS  1e-5f

// ---------------- scratch (static device allocations; no cudaMalloc) -------
__device__ float g_hsrc[NN * HD];     // h_src = feat @ W_src + b_src
__device__ float g_hdst[NN * HD];     // h_dst; overwritten in-place with rst
__device__ float g_z[NN * OUT_DIM];   // fc output
__device__ int   g_deg[NN];
__device__ int   g_cnt[NN];
__device__ int   g_rowptr[NN + 1];
__device__ int   g_ecol[EE];          // src node id per CSR slot
__device__ float g_sum[OUT_DIM], g_sumsq[OUT_DIM];
__device__ float g_mu[OUT_DIM], g_istd[OUT_DIM];

// ---------------- init: zero counters + BN accumulators --------------------
__global__ void k_init() {
    int i = blockIdx.x * blockDim.x + threadIdx.x;
    int stride = gridDim.x * blockDim.x;
    for (int j = i; j < NN; j += stride) { g_deg[j] = 0; g_cnt[j] = 0; }
    if (i < OUT_DIM) { g_sum[i] = 0.f; g_sumsq[i] = 0.f; }
}

// ---------------- degree count ---------------------------------------------
__global__ void k_count(const int* __restrict__ dst) {
    int i = blockIdx.x * blockDim.x + threadIdx.x;
    if (i < EE) atomicAdd(&g_deg[dst[i]], 1);
}

// ---------------- exclusive scan of deg -> rowptr (single block) -----------
__global__ void k_scan() {
    __shared__ int sdata[1024];
    __shared__ int carry;
    int tid = threadIdx.x;
    if (tid == 0) carry = 0;
    __syncthreads();
    for (int base = 0; base < NN; base += 1024) {
        int i = base + tid;
        int v = (i < NN) ? g_deg[i] : 0;
        sdata[tid] = v;
        __syncthreads();
        // Hillis-Steele inclusive scan
        for (int off = 1; off < 1024; off <<= 1) {
            int t = (tid >= off) ? sdata[tid - off] : 0;
            __syncthreads();
            sdata[tid] += t;
            __syncthreads();
        }
        int incl = sdata[tid];
        if (i < NN) g_rowptr[i + 1] = carry + incl;
        if (i == 0) g_rowptr[0] = 0;
        __syncthreads();
        if (tid == 1023) carry += sdata[1023];
        __syncthreads();
    }
}

// ---------------- scatter edges into CSR -----------------------------------
__global__ void k_scatter(const int* __restrict__ src, const int* __restrict__ dst) {
    int i = blockIdx.x * blockDim.x + threadIdx.x;
    if (i < EE) {
        int v = dst[i];
        int pos = g_rowptr[v] + atomicAdd(&g_cnt[v], 1);
        g_ecol[pos] = src[i];
    }
}

// ---------------- tiled fp32 GEMM with bias: C[M,Nn] = A[M,K] @ B[K,Nn] + b -
#define BM 128
#define BN 64
#define BK 16
__global__ __launch_bounds__(256) void k_gemm_bias(
    const float* __restrict__ A, const float* __restrict__ B,
    const float* __restrict__ bias, float* __restrict__ C,
    int M, int Nn, int K)
{
    __shared__ float As[BK][BM];
    __shared__ float Bs[BK][BN];
    int t = threadIdx.x;
    int tm = t >> 4;        // 0..15 -> 8 rows each
    int tn = t & 15;        // 0..15 -> 4 cols each
    int rowBase = blockIdx.y * BM;
    int colBase = blockIdx.x * BN;

    float acc[8][4];
#pragma unroll
    for (int i = 0; i < 8; i++)
#pragma unroll
        for (int j = 0; j < 4; j++) acc[i][j] = 0.f;

    int lrow = t >> 1;            // 0..127
    int lk   = (t & 1) * 8;       // 0 or 8
    int arow = rowBase + lrow;
    if (arow > M - 1) arow = M - 1;
    int bkr = t >> 4;             // 0..15
    int bcn = (t & 15) * 4;       // 0..60

    for (int k0 = 0; k0 < K; k0 += BK) {
        // load A tile (transposed into As[k][m])
        float4 a0 = *(const float4*)&A[arow * K + k0 + lk];
        float4 a1 = *(const float4*)&A[arow * K + k0 + lk + 4];
        As[lk + 0][lrow] = a0.x; As[lk + 1][lrow] = a0.y;
        As[lk + 2][lrow] = a0.z; As[lk + 3][lrow] = a0.w;
        As[lk + 4][lrow] = a1.x; As[lk + 5][lrow] = a1.y;
        As[lk + 6][lrow] = a1.z; As[lk + 7][lrow] = a1.w;
        // load B tile
        *(float4*)&Bs[bkr][bcn] = *(const float4*)&B[(k0 + bkr) * Nn + colBase + bcn];
        __syncthreads();
#pragma unroll
        for (int kk = 0; kk < BK; kk++) {
            float4 b0 = *(const float4*)&Bs[kk][tn * 4];
            float4 c0 = *(const float4*)&As[kk][tm * 8];
            float4 c1 = *(const float4*)&As[kk][tm * 8 + 4];
            float av[8] = {c0.x, c0.y, c0.z, c0.w, c1.x, c1.y, c1.z, c1.w};
            float bv[4] = {b0.x, b0.y, b0.z, b0.w};
#pragma unroll
            for (int i = 0; i < 8; i++)
#pragma unroll
                for (int j = 0; j < 4; j++)
                    acc[i][j] = fmaf(av[i], bv[j], acc[i][j]);
        }
        __syncthreads();
    }

    int gc = colBase + tn * 4;
    float4 bb = *(const float4*)&bias[gc];
#pragma unroll
    for (int i = 0; i < 8; i++) {
        int gr = rowBase + tm * 8 + i;
        if (gr < M) {
            float4 o;
            o.x = acc[i][0] + bb.x;
            o.y = acc[i][1] + bb.y;
            o.z = acc[i][2] + bb.z;
            o.w = acc[i][3] + bb.w;
            *(float4*)&C[gr * Nn + gc] = o;
        }
    }
}

// ---------------- edge aggregation: warp per dst node, online softmax ------
// Reads g_hsrc[src] once per edge; overwrites g_hdst[v] with rst[v]+out_bias.
__global__ __launch_bounds__(256) void k_edge_agg(
    const float* __restrict__ attn, const float* __restrict__ out_bias)
{
    int warp = (blockIdx.x * blockDim.x + threadIdx.x) >> 5;
    int lane = threadIdx.x & 31;
    if (warp >= NN) return;
    int v = warp;
    int base = lane * 8;   // this lane's 8 contiguous dims of the 256-wide row

    float hd[8], at[8];
    {
        float4 d0 = *(const float4*)&g_hdst[v * HD + base];
        float4 d1 = *(const float4*)&g_hdst[v * HD + base + 4];
        hd[0]=d0.x; hd[1]=d0.y; hd[2]=d0.z; hd[3]=d0.w;
        hd[4]=d1.x; hd[5]=d1.y; hd[6]=d1.z; hd[7]=d1.w;
        float4 t0 = *(const float4*)&attn[base];
        float4 t1 = *(const float4*)&attn[base + 4];
        at[0]=t0.x; at[1]=t0.y; at[2]=t0.z; at[3]=t0.w;
        at[4]=t1.x; at[5]=t1.y; at[6]=t1.z; at[7]=t1.w;
    }

    float m = -CUDART_INF_F;
    float s = 0.f;
    float acc[8];
#pragma unroll
    for (int i = 0; i < 8; i++) acc[i] = 0.f;

    int start = g_rowptr[v];
    int end   = g_rowptr[v + 1];
    int u = (start < end) ? g_ecol[start] : 0;
    for (int j = start; j < end; j++) {
        int unext = (j + 1 < end) ? g_ecol[j + 1] : 0;
        const float* hp = &g_hsrc[u * HD + base];
        float4 h0 = *(const float4*)hp;
        float4 h1 = *(const float4*)(hp + 4);
        float hs[8] = {h0.x, h0.y, h0.z, h0.w, h1.x, h1.y, h1.z, h1.w};
        // score partial for this lane's 8 dims
        float e = 0.f;
#pragma unroll
        for (int i = 0; i < 8; i++) {
            float x = hs[i] + hd[i];
            x = (x >= 0.f) ? x : SLOPE * x;
            e = fmaf(at[i], x, e);
        }
        // reduce across the 8 lanes of this head group
        e += __shfl_xor_sync(0xffffffffu, e, 1);
        e += __shfl_xor_sync(0xffffffffu, e, 2);
        e += __shfl_xor_sync(0xffffffffu, e, 4);
        // online softmax update (redundant per-lane within group, identical)
        float nm = fmaxf(m, e);
        float sc = __expf(m - nm);   // 0 on first edge (m=-inf)
        float p  = __expf(e - nm);
        s = s * sc + p;
#pragma unroll
        for (int i = 0; i < 8; i++)
            acc[i] = fmaf(acc[i], sc, p * hs[i]);
        m = nm;
        u = unext;
    }

    float inv = (s > 0.f) ? (1.0f / s) : 0.f;
    float4 ob0 = *(const float4*)&out_bias[base];
    float4 ob1 = *(const float4*)&out_bias[base + 4];
    float4 o0, o1;
    o0.x = acc[0] * inv + ob0.x; o0.y = acc[1] * inv + ob0.y;
    o0.z = acc[2] * inv + ob0.z; o0.w = acc[3] * inv + ob0.w;
    o1.x = acc[4] * inv + ob1.x; o1.y = acc[5] * inv + ob1.y;
    o1.z = acc[6] * inv + ob1.z; o1.w = acc[7] * inv + ob1.w;
    *(float4*)&g_hdst[v * HD + base]     = o0;   // rst written in-place
    *(float4*)&g_hdst[v * HD + base + 4] = o1;
}

// ---------------- BatchNorm partial sums (coalesced) -----------------------
__global__ void k_bn_partial() {
    int c = threadIdx.x & 63;
    int rlane = threadIdx.x >> 6;   // 0..3
    float s = 0.f, s2 = 0.f;
    for (int r = blockIdx.x * 4 + rlane; r < NN; r += gridDim.x * 4) {
        float vv = g_z[r * OUT_DIM + c];
        s += vv; s2 += vv * vv;
    }
    __shared__ float sh[2][4][64];
    sh[0][rlane][c] = s;
    sh[1][rlane][c] = s2;
    __syncthreads();
    if (rlane == 0) {
#pragma unroll
        for (int i = 1; i < 4; i++) { s += sh[0][i][c]; s2 += sh[1][i][c]; }
        atomicAdd(&g_sum[c], s);
        atomicAdd(&g_sumsq[c], s2);
    }
}

__global__ void k_bn_finalize() {
    int c = threadIdx.x;
    if (c < OUT_DIM) {
        float mu = g_sum[c] / (float)NN;
        float var = g_sumsq[c] / (float)NN - mu * mu;
        g_mu[c] = mu;
        g_istd[c] = rsqrtf(var + BN_EPS);
    }
}

// ---------------- apply BN + LeakyReLU -> output ---------------------------
__global__ void k_bn_apply(const float* __restrict__ gamma,
                           const float* __restrict__ beta,
                           float* __restrict__ out)
{
    int i = blockIdx.x * blockDim.x + threadIdx.x;
    int stride = gridDim.x * blockDim.x;
    for (int j = i; j < NN * OUT_DIM; j += stride) {
        int c = j & 63;
        float x = (g_z[j] - g_mu[c]) * g_istd[c] * gamma[c] + beta[c];
        out[j] = (x >= 0.f) ? x : SLOPE * x;
    }
}

// ---------------- launch ----------------------------------------------------
extern "C" void kernel_launch(void* const* d_in, const int* in_sizes, int n_in,
                              void* d_out, int out_size)
{
    const float* feat    = (const float*)d_in[0];
    const int*   src     = (const int*)  d_in[1];
    const int*   dst     = (const int*)  d_in[2];
    const float* W_src   = (const float*)d_in[3];
    const float* b_src   = (const float*)d_in[4];
    const float* W_dst   = (const float*)d_in[5];
    const float* b_dst   = (const float*)d_in[6];
    const float* attn    = (const float*)d_in[7];
    const float* outbias = (const float*)d_in[8];
    const float* fc_W    = (const float*)d_in[9];
    const float* fc_b    = (const float*)d_in[10];
    const float* gamma   = (const float*)d_in[11];
    const float* beta    = (const float*)d_in[12];
    float* out = (float*)d_out;

    float *p_hsrc, *p_hdst, *p_z;
    cudaGetSymbolAddress((void**)&p_hsrc, g_hsrc);
    cudaGetSymbolAddress((void**)&p_hdst, g_hdst);
    cudaGetSymbolAddress((void**)&p_z,    g_z);

    // CSR build
    k_init<<<256, 256>>>();
    k_count<<<(EE + 255) / 256, 256>>>(dst);
    k_scan<<<1, 1024>>>();
    k_scatter<<<(EE + 255) / 256, 256>>>(src, dst);

    // front GEMMs
    dim3 gemmGrid(HD / BN, (NN + BM - 1) / BM);
    k_gemm_bias<<<gemmGrid, 256>>>(feat, W_src, b_src, p_hsrc, NN, HD, IN_DIM);
    k_gemm_bias<<<gemmGrid, 256>>>(feat, W_dst, b_dst, p_hdst, NN, HD, IN_DIM);

    // edge aggregation (warp per node)
    k_edge_agg<<<(NN * 32 + 255) / 256, 256>>>(attn, outbias);

    // trailing fc GEMM: z = rst @ fc_W + fc_b  (rst lives in g_hdst)
    dim3 fcGrid(OUT_DIM / BN, (NN + BM - 1) / BM);
    k_gemm_bias<<<fcGrid, 256>>>(p_hdst, fc_W, fc_b, p_z, NN, OUT_DIM, HD);

    // batch norm + leaky
    k_bn_partial<<<256, 256>>>();
    k_bn_finalize<<<1, 64>>>();
    k_bn_apply<<<512, 256>>>(gamma, beta, out);
}